// round 1
// baseline (speedup 1.0000x reference)
#include <cuda_runtime.h>
#include <math.h>

// ---------------------------------------------------------------------------
// MaskTransformer: fixed shapes
// ---------------------------------------------------------------------------
#define LAYERS 2
#define HEADS  12
#define DMODEL 768
#define DHEAD  64
#define BATCH  8
#define NTOK   1024
#define NCLS   19
#define STOK   1043                 // NTOK + NCLS
#define MTOT   (BATCH*STOK)         // 8344
#define DMLP   3072
#define IMG    512
#define LN_EPS 1e-5f

// ---------------------------------------------------------------------------
// Scratch buffers (static device arrays; no allocation allowed)
// ---------------------------------------------------------------------------
__device__ float g_Tmp[BATCH*NTOK*DMODEL];   // proj_dec output (patch tokens)
__device__ float g_X  [MTOT*DMODEL];         // residual stream
__device__ float g_H  [MTOT*DMODEL];         // LN output
__device__ float g_Q  [MTOT*DMODEL];
__device__ float g_K  [MTOT*DMODEL];
__device__ float g_V  [MTOT*DMODEL];
__device__ float g_O  [MTOT*DMODEL];
__device__ float g_M1 [MTOT*DMLP];           // MLP hidden
__device__ float g_Pln[BATCH*NTOK*DMODEL];   // dec-LN patches
__device__ float g_PP [BATCH*NTOK*DMODEL];   // patches @ proj_patch
__device__ float g_Cln[BATCH*NCLS*DMODEL];   // dec-LN cls
__device__ float g_CP [BATCH*NCLS*DMODEL];   // cls @ proj_classes
__device__ float g_CN [BATCH*NCLS*DMODEL];   // normalized cls
__device__ float g_MS [BATCH*NCLS*NTOK];     // mask logits (b,c,n) after mask-LN

// ---------------------------------------------------------------------------
// Block reduce (256 threads)
// ---------------------------------------------------------------------------
__device__ __forceinline__ float block_reduce_sum(float v, float* scratch /*>=8*/) {
    int lane = threadIdx.x & 31, w = threadIdx.x >> 5;
#pragma unroll
    for (int o = 16; o; o >>= 1) v += __shfl_xor_sync(0xffffffffu, v, o);
    if (!lane) scratch[w] = v;
    __syncthreads();
    float r = (threadIdx.x < 8) ? scratch[threadIdx.x] : 0.f;
    if (w == 0) {
#pragma unroll
        for (int o = 4; o; o >>= 1) r += __shfl_xor_sync(0xffffffffu, r, o);
        if (!lane) scratch[0] = r;
    }
    __syncthreads();
    r = scratch[0];
    __syncthreads();
    return r;
}

// ---------------------------------------------------------------------------
// Generic SGEMM: C[M,N] = A[M,K](lda) @ B[K,N](ldb) (+bias)(+gelu)(+=C)
// 128x128 tile, BK=8, 256 threads, 8x8 per thread
// flags: bit0 = exact GELU, bit1 = accumulate into C
// ---------------------------------------------------------------------------
__global__ __launch_bounds__(256) void sgemm128(
    const float* __restrict__ A, int lda,
    const float* __restrict__ B, int ldb,
    const float* __restrict__ bias,
    float* __restrict__ C, int ldc,
    int M, int N, int K, int flags)
{
    __shared__ float As[8][128];
    __shared__ float Bs[8][128];
    int tid = threadIdx.x;
    int tx = tid & 15, ty = tid >> 4;
    int row0 = blockIdx.y * 128, col0 = blockIdx.x * 128;

    float acc[8][8];
#pragma unroll
    for (int i = 0; i < 8; i++)
#pragma unroll
        for (int j = 0; j < 8; j++) acc[i][j] = 0.f;

    int la_r = tid >> 1;            // 0..127
    int la_k = (tid & 1) * 4;       // 0 or 4
    int lb_k = tid >> 5;            // 0..7
    int lb_c = (tid & 31) * 4;      // 0..124

    for (int kt = 0; kt < K; kt += 8) {
        // load A tile (K always multiple of 8 in this model)
        float4 av = make_float4(0.f, 0.f, 0.f, 0.f);
        int ar = row0 + la_r;
        if (ar < M) av = *(const float4*)(A + (size_t)ar * lda + kt + la_k);
        As[la_k + 0][la_r] = av.x;
        As[la_k + 1][la_r] = av.y;
        As[la_k + 2][la_r] = av.z;
        As[la_k + 3][la_r] = av.w;
        // load B tile
        float4 bv = make_float4(0.f, 0.f, 0.f, 0.f);
        int bc = col0 + lb_c;
        if (bc + 3 < N) {
            bv = *(const float4*)(B + (size_t)(kt + lb_k) * ldb + bc);
        } else {
            float t0 = (bc + 0 < N) ? B[(size_t)(kt + lb_k) * ldb + bc + 0] : 0.f;
            float t1 = (bc + 1 < N) ? B[(size_t)(kt + lb_k) * ldb + bc + 1] : 0.f;
            float t2 = (bc + 2 < N) ? B[(size_t)(kt + lb_k) * ldb + bc + 2] : 0.f;
            bv = make_float4(t0, t1, t2, 0.f);
        }
        *(float4*)&Bs[lb_k][lb_c] = bv;
        __syncthreads();
#pragma unroll
        for (int kk = 0; kk < 8; kk++) {
            float a[8], bb[8];
            *(float4*)&a[0] = *(float4*)&As[kk][ty * 8];
            *(float4*)&a[4] = *(float4*)&As[kk][ty * 8 + 4];
            *(float4*)&bb[0] = *(float4*)&Bs[kk][tx * 8];
            *(float4*)&bb[4] = *(float4*)&Bs[kk][tx * 8 + 4];
#pragma unroll
            for (int i = 0; i < 8; i++)
#pragma unroll
                for (int j = 0; j < 8; j++)
                    acc[i][j] = fmaf(a[i], bb[j], acc[i][j]);
        }
        __syncthreads();
    }

#pragma unroll
    for (int i = 0; i < 8; i++) {
        int r = row0 + ty * 8 + i;
        if (r >= M) break;
#pragma unroll
        for (int j = 0; j < 8; j++) {
            int c = col0 + tx * 8 + j;
            if (c >= N) break;
            float v = acc[i][j];
            if (bias) v += bias[c];
            if (flags & 1) v = 0.5f * v * (1.f + erff(v * 0.70710678118654752f));
            float* cp = C + (size_t)r * ldc + c;
            if (flags & 2) v += *cp;
            *cp = v;
        }
    }
}

// ---------------------------------------------------------------------------
// Assemble X = concat(proj_dec(x), cls_emb broadcast) over tokens
// ---------------------------------------------------------------------------
__global__ void assemble_kernel(const float* __restrict__ tmp,
                                const float* __restrict__ cls,
                                float* __restrict__ X)
{
    int i = blockIdx.x * blockDim.x + threadIdx.x;
    if (i >= MTOT * DMODEL) return;
    int row = i / DMODEL, col = i - row * DMODEL;
    int b = row / STOK, s = row - b * STOK;
    float v = (s < NTOK) ? tmp[((size_t)b * NTOK + s) * DMODEL + col]
                         : cls[(size_t)(s - NTOK) * DMODEL + col];
    X[i] = v;
}

// ---------------------------------------------------------------------------
// LayerNorm over 768, one block (256 thr) per row
// ---------------------------------------------------------------------------
__global__ __launch_bounds__(256) void ln768_kernel(
    const float* __restrict__ X, const float* __restrict__ g,
    const float* __restrict__ bb, float* __restrict__ Y)
{
    __shared__ float scr[8];
    int row = blockIdx.x, t = threadIdx.x;
    const float* x = X + (size_t)row * DMODEL;
    float v0 = x[t], v1 = x[t + 256], v2 = x[t + 512];
    float s  = block_reduce_sum(v0 + v1 + v2, scr);
    float sq = block_reduce_sum(v0 * v0 + v1 * v1 + v2 * v2, scr);
    float mean = s * (1.f / 768.f);
    float var  = sq * (1.f / 768.f) - mean * mean;
    float inv  = rsqrtf(var + LN_EPS);
    float* y = Y + (size_t)row * DMODEL;
    y[t]       = (v0 - mean) * inv * g[t]       + bb[t];
    y[t + 256] = (v1 - mean) * inv * g[t + 256] + bb[t + 256];
    y[t + 512] = (v2 - mean) * inv * g[t + 512] + bb[t + 512];
}

// Decoder LN with split outputs: patches -> P (contiguous), cls -> C
__global__ __launch_bounds__(256) void lndec_kernel(
    const float* __restrict__ X, const float* __restrict__ g,
    const float* __restrict__ bb, float* __restrict__ P, float* __restrict__ Cc)
{
    __shared__ float scr[8];
    int row = blockIdx.x, t = threadIdx.x;
    const float* x = X + (size_t)row * DMODEL;
    float v0 = x[t], v1 = x[t + 256], v2 = x[t + 512];
    float s  = block_reduce_sum(v0 + v1 + v2, scr);
    float sq = block_reduce_sum(v0 * v0 + v1 * v1 + v2 * v2, scr);
    float mean = s * (1.f / 768.f);
    float var  = sq * (1.f / 768.f) - mean * mean;
    float inv  = rsqrtf(var + LN_EPS);
    int b = row / STOK, sl = row - b * STOK;
    float* y = (sl < NTOK) ? P + ((size_t)b * NTOK + sl) * DMODEL
                           : Cc + ((size_t)b * NCLS + (sl - NTOK)) * DMODEL;
    y[t]       = (v0 - mean) * inv * g[t]       + bb[t];
    y[t + 256] = (v1 - mean) * inv * g[t + 256] + bb[t + 256];
    y[t + 512] = (v2 - mean) * inv * g[t + 512] + bb[t + 512];
}

// L2-normalize rows of 768
__global__ __launch_bounds__(256) void l2n_kernel(const float* __restrict__ in,
                                                  float* __restrict__ out)
{
    __shared__ float scr[8];
    int row = blockIdx.x, t = threadIdx.x;
    const float* x = in + (size_t)row * DMODEL;
    float v0 = x[t], v1 = x[t + 256], v2 = x[t + 512];
    float sq = block_reduce_sum(v0 * v0 + v1 * v1 + v2 * v2, scr);
    float inv = rsqrtf(sq);
    float* y = out + (size_t)row * DMODEL;
    y[t] = v0 * inv; y[t + 256] = v1 * inv; y[t + 512] = v2 * inv;
}

// Residual add (float4)
__global__ void add_kernel(float* __restrict__ X, const float* __restrict__ O)
{
    int i = blockIdx.x * blockDim.x + threadIdx.x;
    float4 a = ((float4*)X)[i];
    float4 o = ((const float4*)O)[i];
    a.x += o.x; a.y += o.y; a.z += o.z; a.w += o.w;
    ((float4*)X)[i] = a;
}

// ---------------------------------------------------------------------------
// QKV block-diagonal projection: one block = (64-row tile, head, q/k/v)
// ---------------------------------------------------------------------------
__global__ __launch_bounds__(256) void qkv_kernel(
    const float* __restrict__ Hb,
    const float* __restrict__ qW, const float* __restrict__ qb,
    const float* __restrict__ kW, const float* __restrict__ kb,
    const float* __restrict__ vW, const float* __restrict__ vb,
    int layer, float* __restrict__ Qo, float* __restrict__ Ko, float* __restrict__ Vo)
{
    __shared__ float Ws[64 * 64];
    __shared__ float Asm[64 * 65];
    int h = blockIdx.y, which = blockIdx.z;
    const float* W; const float* bias; float* Out;
    if (which == 0) { W = qW; bias = qb; Out = Qo; }
    else if (which == 1) { W = kW; bias = kb; Out = Ko; }
    else { W = vW; bias = vb; Out = Vo; }
    W    += ((size_t)layer * HEADS + h) * 4096;
    bias += ((size_t)layer * HEADS + h) * 64;
    int r0 = blockIdx.x * 64;
    int t = threadIdx.x;
    for (int i = t; i < 4096; i += 256) Ws[i] = W[i];
    for (int i = t; i < 4096; i += 256) {
        int r = i >> 6, d = i & 63;
        Asm[r * 65 + d] = (r0 + r < MTOT) ? Hb[(size_t)(r0 + r) * DMODEL + h * 64 + d] : 0.f;
    }
    __syncthreads();
    int tx = t & 15, ty = t >> 4;
    float acc[4][4];
#pragma unroll
    for (int i = 0; i < 4; i++)
#pragma unroll
        for (int j = 0; j < 4; j++) acc[i][j] = 0.f;
#pragma unroll 4
    for (int d = 0; d < 64; d++) {
        float a[4], w[4];
#pragma unroll
        for (int i = 0; i < 4; i++) a[i] = Asm[(ty * 4 + i) * 65 + d];
#pragma unroll
        for (int j = 0; j < 4; j++) w[j] = Ws[d * 64 + tx * 4 + j];
#pragma unroll
        for (int i = 0; i < 4; i++)
#pragma unroll
            for (int j = 0; j < 4; j++) acc[i][j] = fmaf(a[i], w[j], acc[i][j]);
    }
#pragma unroll
    for (int i = 0; i < 4; i++) {
        int r = r0 + ty * 4 + i;
        if (r >= MTOT) continue;
#pragma unroll
        for (int j = 0; j < 4; j++)
            Out[(size_t)r * DMODEL + h * 64 + tx * 4 + j] = acc[i][j] + bias[tx * 4 + j];
    }
}

// ---------------------------------------------------------------------------
// Attention: block = (b, h, 16-query tile). Exact softmax with full score row
// in SMEM. dynamic smem: sc[16][SPAD] + qs[16][64] + kv[64][65]
// ---------------------------------------------------------------------------
#define QT 16
#define SPAD 1044
#define ATTN_SMEM ((QT*SPAD + QT*64 + 64*65)*4)

__global__ __launch_bounds__(256) void attn_kernel(
    const float* __restrict__ Q, const float* __restrict__ K,
    const float* __restrict__ V, float* __restrict__ O)
{
    extern __shared__ float sm[];
    float* sc = sm;
    float* qs = sm + QT * SPAD;
    float* kv = qs + QT * 64;
    int b = blockIdx.z, h = blockIdx.y;
    int q0 = blockIdx.x * QT;
    int t = threadIdx.x;
    size_t base = ((size_t)b * STOK) * DMODEL + h * 64;

    for (int i = t; i < QT * 64; i += 256) {
        int q = i >> 6, d = i & 63;
        qs[q * 64 + d] = (q0 + q < STOK) ? Q[base + (size_t)(q0 + q) * DMODEL + d] : 0.f;
    }
    __syncthreads();

    int kl  = t & 63;
    int qb4 = (t >> 6) << 2;
    for (int k0 = 0; k0 < STOK; k0 += 64) {
        for (int i = t; i < 4096; i += 256) {
            int r = i >> 6, d = i & 63;
            kv[r * 65 + d] = (k0 + r < STOK) ? K[base + (size_t)(k0 + r) * DMODEL + d] : 0.f;
        }
        __syncthreads();
        if (k0 + kl < STOK) {
            float a0 = 0.f, a1 = 0.f, a2 = 0.f, a3 = 0.f;
#pragma unroll 8
            for (int d = 0; d < 64; d++) {
                float kv_ = kv[kl * 65 + d];
                a0 = fmaf(qs[(qb4 + 0) * 64 + d], kv_, a0);
                a1 = fmaf(qs[(qb4 + 1) * 64 + d], kv_, a1);
                a2 = fmaf(qs[(qb4 + 2) * 64 + d], kv_, a2);
                a3 = fmaf(qs[(qb4 + 3) * 64 + d], kv_, a3);
            }
            int kc = k0 + kl;
            sc[(qb4 + 0) * SPAD + kc] = a0 * 0.125f;
            sc[(qb4 + 1) * SPAD + kc] = a1 * 0.125f;
            sc[(qb4 + 2) * SPAD + kc] = a2 * 0.125f;
            sc[(qb4 + 3) * SPAD + kc] = a3 * 0.125f;
        }
        __syncthreads();
    }

    // softmax over keys; warp w handles rows w, w+8
    int w = t >> 5, lane = t & 31;
    for (int q = w; q < QT; q += 8) {
        if (q0 + q >= STOK) continue;
        float mx = -1e30f;
        for (int k = lane; k < STOK; k += 32) mx = fmaxf(mx, sc[q * SPAD + k]);
#pragma unroll
        for (int o = 16; o; o >>= 1) mx = fmaxf(mx, __shfl_xor_sync(0xffffffffu, mx, o));
        float s = 0.f;
        for (int k = lane; k < STOK; k += 32) {
            float e = __expf(sc[q * SPAD + k] - mx);
            sc[q * SPAD + k] = e;
            s += e;
        }
#pragma unroll
        for (int o = 16; o; o >>= 1) s += __shfl_xor_sync(0xffffffffu, s, o);
        float inv = 1.f / s;
        for (int k = lane; k < STOK; k += 32) sc[q * SPAD + k] *= inv;
    }
    __syncthreads();

    // O = P @ V
    int qv = t >> 4;
    int dd = (t & 15) << 2;
    float o0 = 0.f, o1 = 0.f, o2 = 0.f, o3 = 0.f;
    for (int k0 = 0; k0 < STOK; k0 += 64) {
        for (int i = t; i < 4096; i += 256) {
            int r = i >> 6, d = i & 63;
            kv[r * 65 + d] = (k0 + r < STOK) ? V[base + (size_t)(k0 + r) * DMODEL + d] : 0.f;
        }
        __syncthreads();
        int kmax = min(64, STOK - k0);
        for (int kk = 0; kk < kmax; kk++) {
            float p = sc[qv * SPAD + k0 + kk];
            o0 = fmaf(p, kv[kk * 65 + dd + 0], o0);
            o1 = fmaf(p, kv[kk * 65 + dd + 1], o1);
            o2 = fmaf(p, kv[kk * 65 + dd + 2], o2);
            o3 = fmaf(p, kv[kk * 65 + dd + 3], o3);
        }
        __syncthreads();
    }
    if (q0 + qv < STOK) {
        float* op = O + base + (size_t)(q0 + qv) * DMODEL + dd;
        op[0] = o0; op[1] = o1; op[2] = o2; op[3] = o3;
    }
}

// ---------------------------------------------------------------------------
// Cosine-sim mask logits + mask LayerNorm, output as (b, c, n)
// block = (n, b): dots of (unnormalized patch)/||patch|| with normalized cls
// ---------------------------------------------------------------------------
__global__ __launch_bounds__(256) void classdot_ln_kernel(
    const float* __restrict__ pp, const float* __restrict__ cn,
    const float* __restrict__ mg, const float* __restrict__ mb,
    float* __restrict__ ms)
{
    __shared__ float p[768];
    __shared__ float dots[32];
    __shared__ float mv[2];
    __shared__ float scr[8];
    int n = blockIdx.x, b = blockIdx.y;
    int t = threadIdx.x;
    const float* prow = pp + ((size_t)b * NTOK + n) * DMODEL;
    float a0 = prow[t], a1 = prow[t + 256], a2 = prow[t + 512];
    p[t] = a0; p[t + 256] = a1; p[t + 512] = a2;
    float sq = block_reduce_sum(a0 * a0 + a1 * a1 + a2 * a2, scr);
    float pinv = rsqrtf(sq);
    __syncthreads();
    int w = t >> 5, lane = t & 31;
    for (int c = w; c < NCLS; c += 8) {
        const float* crow = cn + ((size_t)b * NCLS + c) * DMODEL;
        float s = 0.f;
        for (int d = lane; d < DMODEL; d += 32) s += p[d] * crow[d];
#pragma unroll
        for (int o = 16; o; o >>= 1) s += __shfl_xor_sync(0xffffffffu, s, o);
        if (!lane) dots[c] = s * pinv;
    }
    __syncthreads();
    if (t == 0) {
        float m = 0.f;
        for (int c = 0; c < NCLS; c++) m += dots[c];
        m *= (1.f / NCLS);
        float v = 0.f;
        for (int c = 0; c < NCLS; c++) { float d = dots[c] - m; v += d * d; }
        v *= (1.f / NCLS);
        mv[0] = m; mv[1] = rsqrtf(v + LN_EPS);
    }
    __syncthreads();
    if (t < NCLS)
        ms[((size_t)b * NCLS + t) * NTOK + n] = (dots[t] - mv[0]) * mv[1] * mg[t] + mb[t];
}

// ---------------------------------------------------------------------------
// Bilinear 32x32 -> 512x512 (jax half-pixel centers; edge == clamp)
// each thread writes 4 consecutive output pixels (float4)
// ---------------------------------------------------------------------------
__global__ void resize_kernel(const float* __restrict__ ms, float* __restrict__ out)
{
    int i = blockIdx.x * blockDim.x + threadIdx.x;   // 8*19*512*128 threads
    int xq = i & 127;
    int r  = i >> 7;
    int oy = r & 511; r >>= 9;
    int c  = r % NCLS;
    int b  = r / NCLS;
    const float* m = ms + ((size_t)b * NCLS + c) * NTOK;

    float fy = oy * 0.0625f - 0.46875f;
    float fyf = floorf(fy);
    float wy = fy - fyf;
    int y0 = (int)fyf, y1 = y0 + 1;
    y0 = max(0, min(31, y0));
    y1 = max(0, min(31, y1));
    const float* r0p = m + y0 * 32;
    const float* r1p = m + y1 * 32;

    float4 o4;
    float* po = (float*)&o4;
    int ox0 = xq * 4;
#pragma unroll
    for (int j = 0; j < 4; j++) {
        float fx = (ox0 + j) * 0.0625f - 0.46875f;
        float fxf = floorf(fx);
        float wx = fx - fxf;
        int x0 = (int)fxf, x1 = x0 + 1;
        x0 = max(0, min(31, x0));
        x1 = max(0, min(31, x1));
        float top = (1.f - wx) * r0p[x0] + wx * r0p[x1];
        float bot = (1.f - wx) * r1p[x0] + wx * r1p[x1];
        po[j] = (1.f - wy) * top + wy * bot;
    }
    *(float4*)(out + (((size_t)b * NCLS + c) * IMG + oy) * IMG + ox0) = o4;
}

// ---------------------------------------------------------------------------
// Host launcher
// ---------------------------------------------------------------------------
extern "C" void kernel_launch(void* const* d_in, const int* in_sizes, int n_in,
                              void* d_out, int out_size)
{
    const float* x          = (const float*)d_in[0];
    const float* proj_dec_W = (const float*)d_in[1];
    const float* proj_dec_b = (const float*)d_in[2];
    const float* cls_emb    = (const float*)d_in[3];
    const float* ln1_g      = (const float*)d_in[4];
    const float* ln1_b      = (const float*)d_in[5];
    const float* qW         = (const float*)d_in[6];
    const float* qb         = (const float*)d_in[7];
    const float* kW         = (const float*)d_in[8];
    const float* kb         = (const float*)d_in[9];
    const float* vW         = (const float*)d_in[10];
    const float* vb         = (const float*)d_in[11];
    const float* ln2_g      = (const float*)d_in[12];
    const float* ln2_b      = (const float*)d_in[13];
    const float* mlp_W1     = (const float*)d_in[14];
    const float* mlp_b1     = (const float*)d_in[15];
    const float* mlp_W2     = (const float*)d_in[16];
    const float* mlp_b2     = (const float*)d_in[17];
    const float* proj_patch = (const float*)d_in[18];
    const float* proj_cls   = (const float*)d_in[19];
    const float* dec_g      = (const float*)d_in[20];
    const float* dec_b      = (const float*)d_in[21];
    const float* mask_g     = (const float*)d_in[22];
    const float* mask_b     = (const float*)d_in[23];
    float* out = (float*)d_out;

    float *pTmp, *pX, *pH, *pQ, *pK, *pV, *pO, *pM1, *pPln, *pPP, *pCln, *pCP, *pCN, *pMS;
    cudaGetSymbolAddress((void**)&pTmp, g_Tmp);
    cudaGetSymbolAddress((void**)&pX,   g_X);
    cudaGetSymbolAddress((void**)&pH,   g_H);
    cudaGetSymbolAddress((void**)&pQ,   g_Q);
    cudaGetSymbolAddress((void**)&pK,   g_K);
    cudaGetSymbolAddress((void**)&pV,   g_V);
    cudaGetSymbolAddress((void**)&pO,   g_O);
    cudaGetSymbolAddress((void**)&pM1,  g_M1);
    cudaGetSymbolAddress((void**)&pPln, g_Pln);
    cudaGetSymbolAddress((void**)&pPP,  g_PP);
    cudaGetSymbolAddress((void**)&pCln, g_Cln);
    cudaGetSymbolAddress((void**)&pCP,  g_CP);
    cudaGetSymbolAddress((void**)&pCN,  g_CN);
    cudaGetSymbolAddress((void**)&pMS,  g_MS);

    cudaFuncSetAttribute(attn_kernel, cudaFuncAttributeMaxDynamicSharedMemorySize, ATTN_SMEM);

    // 1) proj_dec: Tmp = x @ W + b   (M=8192, N=768, K=768)
    sgemm128<<<dim3(6, 64), 256>>>(x, DMODEL, proj_dec_W, DMODEL, proj_dec_b,
                                   pTmp, DMODEL, BATCH * NTOK, DMODEL, DMODEL, 0);
    // 2) assemble X = concat(Tmp, cls_emb)
    assemble_kernel<<<(MTOT * DMODEL + 255) / 256, 256>>>(pTmp, cls_emb, pX);

    for (int l = 0; l < LAYERS; l++) {
        // LN1
        ln768_kernel<<<MTOT, 256>>>(pX, ln1_g + l * DMODEL, ln1_b + l * DMODEL, pH);
        // QKV (block-diagonal per head)
        qkv_kernel<<<dim3((MTOT + 63) / 64, HEADS, 3), 256>>>(
            pH, qW, qb, kW, kb, vW, vb, l, pQ, pK, pV);
        // attention
        attn_kernel<<<dim3((STOK + QT - 1) / QT, HEADS, BATCH), 256, ATTN_SMEM>>>(pQ, pK, pV, pO);
        // residual
        add_kernel<<<MTOT * DMODEL / 4 / 256, 256>>>(pX, pO);
        // LN2
        ln768_kernel<<<MTOT, 256>>>(pX, ln2_g + l * DMODEL, ln2_b + l * DMODEL, pH);
        // MLP
        sgemm128<<<dim3(24, (MTOT + 127) / 128), 256>>>(
            pH, DMODEL, mlp_W1 + (size_t)l * DMODEL * DMLP, DMLP, mlp_b1 + l * DMLP,
            pM1, DMLP, MTOT, DMLP, DMODEL, 1 /*gelu*/);
        sgemm128<<<dim3(6, (MTOT + 127) / 128), 256>>>(
            pM1, DMLP, mlp_W2 + (size_t)l * DMLP * DMODEL, DMODEL, mlp_b2 + l * DMODEL,
            pX, DMODEL, MTOT, DMODEL, DMLP, 2 /*accumulate*/);
    }

    // decoder LN with split outputs
    lndec_kernel<<<MTOT, 256>>>(pX, dec_g, dec_b, pPln, pCln);
    // projections
    sgemm128<<<dim3(6, 64), 256>>>(pPln, DMODEL, proj_patch, DMODEL, nullptr,
                                   pPP, DMODEL, BATCH * NTOK, DMODEL, DMODEL, 0);
    sgemm128<<<dim3(6, 2), 256>>>(pCln, DMODEL, proj_cls, DMODEL, nullptr,
                                  pCP, DMODEL, BATCH * NCLS, DMODEL, DMODEL, 0);
    // normalize cls rows
    l2n_kernel<<<BATCH * NCLS, 256>>>(pCP, pCN);
    // mask logits + mask LN (patch normalization folded in)
    classdot_ln_kernel<<<dim3(NTOK, BATCH), 256>>>(pPP, pCN, mask_g, mask_b, pMS);
    // bilinear upsample 32->512
    resize_kernel<<<BATCH * NCLS * IMG * (IMG / 4) / 256, 256>>>(pMS, out);
}

// round 2
// speedup vs baseline: 1.0970x; 1.0970x over previous
#include <cuda_runtime.h>
#include <stdint.h>
#include <math.h>

// ---------------------------------------------------------------------------
// MaskTransformer: fixed shapes
// ---------------------------------------------------------------------------
#define LAYERS 2
#define HEADS  12
#define DMODEL 768
#define DHEAD  64
#define BATCH  8
#define NTOK   1024
#define NCLS   19
#define STOK   1043                 // NTOK + NCLS
#define MTOT   (BATCH*STOK)         // 8344
#define DMLP   3072
#define IMG    512
#define LN_EPS 1e-5f

// ---------------------------------------------------------------------------
// Scratch buffers
// ---------------------------------------------------------------------------
__device__ float g_Tmp[BATCH*NTOK*DMODEL];
__device__ float g_X  [MTOT*DMODEL];
__device__ float g_H  [MTOT*DMODEL];
__device__ float g_Q  [MTOT*DMODEL];
__device__ float g_K  [MTOT*DMODEL];
__device__ float g_V  [MTOT*DMODEL];
__device__ float g_O  [MTOT*DMODEL];
__device__ float g_M1 [MTOT*DMLP];
__device__ float g_Pln[BATCH*NTOK*DMODEL];
__device__ float g_PP [BATCH*NTOK*DMODEL];
__device__ float g_Cln[BATCH*NCLS*DMODEL];
__device__ float g_CP [BATCH*NCLS*DMODEL];
__device__ float g_CN [BATCH*NCLS*DMODEL];
__device__ float g_MS [BATCH*NCLS*NTOK];

// ---------------------------------------------------------------------------
// helpers
// ---------------------------------------------------------------------------
__device__ __forceinline__ float block_reduce_sum(float v, float* scratch) {
    int lane = threadIdx.x & 31, w = threadIdx.x >> 5;
#pragma unroll
    for (int o = 16; o; o >>= 1) v += __shfl_xor_sync(0xffffffffu, v, o);
    if (!lane) scratch[w] = v;
    __syncthreads();
    float r = (threadIdx.x < 8) ? scratch[threadIdx.x] : 0.f;
    if (w == 0) {
#pragma unroll
        for (int o = 4; o; o >>= 1) r += __shfl_xor_sync(0xffffffffu, r, o);
        if (!lane) scratch[0] = r;
    }
    __syncthreads();
    r = scratch[0];
    __syncthreads();
    return r;
}

__device__ __forceinline__ uint32_t tf32_rna(float f) {
    uint32_t u;
    asm("cvt.rna.tf32.f32 %0, %1;" : "=r"(u) : "f"(f));
    return u;
}

__device__ __forceinline__ void mma_tf32(float* c, const uint32_t* a, const uint32_t* b) {
    asm volatile(
        "mma.sync.aligned.m16n8k8.row.col.f32.tf32.tf32.f32 "
        "{%0,%1,%2,%3}, {%4,%5,%6,%7}, {%8,%9}, {%0,%1,%2,%3};"
        : "+f"(c[0]), "+f"(c[1]), "+f"(c[2]), "+f"(c[3])
        : "r"(a[0]), "r"(a[1]), "r"(a[2]), "r"(a[3]), "r"(b[0]), "r"(b[1]));
}

// ---------------------------------------------------------------------------
// TF32x3 tensor-core GEMM: C[M,N] = A[M,K] @ B[K,N] (+bias)(+gelu)(+=C)
// tile 128x128x32, 256 threads, warp grid 4(M)x2(N), warp tile 32x64
// Error-compensated: A=Ah+Al, B=Bh+Bl; C += Al*Bh + Ah*Bl + Ah*Bh (fp32 acc)
// flags: bit0 = exact GELU, bit1 = accumulate into C
// ---------------------------------------------------------------------------
#define SPITCH 136
#define AS(k,m) ((k)*SPITCH + (m))
#define GEMM_SMEM (4*32*SPITCH*4)

__global__ __launch_bounds__(256) void gemm_tf32x3(
    const float* __restrict__ A, int lda,
    const float* __restrict__ B, int ldb,
    const float* __restrict__ bias,
    float* __restrict__ C, int ldc,
    int M, int N, int K, int flags)
{
    extern __shared__ uint32_t sh[];
    uint32_t* sAh = sh;
    uint32_t* sAl = sAh + 32 * SPITCH;
    uint32_t* sBh = sAl + 32 * SPITCH;
    uint32_t* sBl = sBh + 32 * SPITCH;

    int tid = threadIdx.x, wid = tid >> 5, lane = tid & 31;
    int g = lane >> 2, t = lane & 3;
    int wm = (wid & 3) * 32, wn = (wid >> 2) * 64;
    int row0 = blockIdx.y * 128, col0 = blockIdx.x * 128;

    float acc[2][8][4];
#pragma unroll
    for (int i = 0; i < 2; i++)
#pragma unroll
        for (int j = 0; j < 8; j++)
#pragma unroll
            for (int q = 0; q < 4; q++) acc[i][j][q] = 0.f;

    // loader indices
    int m_l = tid & 127, kgA = (tid >> 7) * 16;     // A: 4 float4 along K
    int k_lb = tid >> 3, n_lb = (tid & 7) * 16;     // B: 4 float4 along N

    float4 apf[4], bpf[4];

    auto g_load = [&](int kt) {
        int ar = row0 + m_l;
        if (ar < M) {
            const float* Ap = A + (size_t)ar * lda + kt + kgA;
#pragma unroll
            for (int i = 0; i < 4; i++) apf[i] = *(const float4*)(Ap + 4 * i);
        } else {
#pragma unroll
            for (int i = 0; i < 4; i++) apf[i] = make_float4(0.f, 0.f, 0.f, 0.f);
        }
        const float* Bp = B + (size_t)(kt + k_lb) * ldb + col0 + n_lb;
#pragma unroll
        for (int i = 0; i < 4; i++) bpf[i] = *(const float4*)(Bp + 4 * i);
    };

    auto s_store = [&]() {
#pragma unroll
        for (int i = 0; i < 4; i++) {
            const float* v = (const float*)&apf[i];
#pragma unroll
            for (int j = 0; j < 4; j++) {
                float x = v[j];
                uint32_t h = tf32_rna(x);
                float r = x - __uint_as_float(h);
                int idx = AS(kgA + 4 * i + j, m_l);
                sAh[idx] = h;
                sAl[idx] = tf32_rna(r);
            }
        }
#pragma unroll
        for (int i = 0; i < 4; i++) {
            const float* v = (const float*)&bpf[i];
#pragma unroll
            for (int j = 0; j < 4; j++) {
                float x = v[j];
                uint32_t h = tf32_rna(x);
                float r = x - __uint_as_float(h);
                int idx = AS(k_lb, n_lb + 4 * i + j);
                sBh[idx] = h;
                sBl[idx] = tf32_rna(r);
            }
        }
    };

    auto compute = [&]() {
#pragma unroll
        for (int ks = 0; ks < 4; ks++) {
            int kb = ks * 8;
            uint32_t ah[2][4], al[2][4];
#pragma unroll
            for (int mt = 0; mt < 2; mt++) {
                int r = wm + mt * 16 + g;
                ah[mt][0] = sAh[AS(kb + t,     r)];
                ah[mt][1] = sAh[AS(kb + t,     r + 8)];
                ah[mt][2] = sAh[AS(kb + t + 4, r)];
                ah[mt][3] = sAh[AS(kb + t + 4, r + 8)];
                al[mt][0] = sAl[AS(kb + t,     r)];
                al[mt][1] = sAl[AS(kb + t,     r + 8)];
                al[mt][2] = sAl[AS(kb + t + 4, r)];
                al[mt][3] = sAl[AS(kb + t + 4, r + 8)];
            }
#pragma unroll
            for (int nt = 0; nt < 8; nt++) {
                int c = wn + nt * 8 + g;
                uint32_t bh[2], bl[2];
                bh[0] = sBh[AS(kb + t,     c)];
                bh[1] = sBh[AS(kb + t + 4, c)];
                bl[0] = sBl[AS(kb + t,     c)];
                bl[1] = sBl[AS(kb + t + 4, c)];
#pragma unroll
                for (int mt = 0; mt < 2; mt++) {
                    mma_tf32(acc[mt][nt], al[mt], bh);   // Al*Bh
                    mma_tf32(acc[mt][nt], ah[mt], bl);   // Ah*Bl
                    mma_tf32(acc[mt][nt], ah[mt], bh);   // Ah*Bh
                }
            }
        }
    };

    g_load(0);
    s_store();
    __syncthreads();
    for (int kt = 0; kt < K; kt += 32) {
        bool more = (kt + 32) < K;
        if (more) g_load(kt + 32);
        compute();
        __syncthreads();
        if (more) { s_store(); __syncthreads(); }
    }

    // epilogue
#pragma unroll
    for (int mt = 0; mt < 2; mt++) {
#pragma unroll
        for (int nt = 0; nt < 8; nt++) {
            int c = col0 + wn + nt * 8 + 2 * t;
#pragma unroll
            for (int half = 0; half < 2; half++) {
                int r = row0 + wm + mt * 16 + g + half * 8;
                if (r >= M) continue;
                float v0 = acc[mt][nt][half * 2 + 0];
                float v1 = acc[mt][nt][half * 2 + 1];
                if (bias) { v0 += bias[c]; v1 += bias[c + 1]; }
                if (flags & 1) {
                    v0 = 0.5f * v0 * (1.f + erff(v0 * 0.70710678118654752f));
                    v1 = 0.5f * v1 * (1.f + erff(v1 * 0.70710678118654752f));
                }
                float* p = C + (size_t)r * ldc + c;
                if (flags & 2) { v0 += p[0]; v1 += p[1]; }
                p[0] = v0; p[1] = v1;
            }
        }
    }
}

// ---------------------------------------------------------------------------
// Assemble X = concat(proj_dec(x), cls_emb broadcast)
// ---------------------------------------------------------------------------
__global__ void assemble_kernel(const float* __restrict__ tmp,
                                const float* __restrict__ cls,
                                float* __restrict__ X)
{
    int i = blockIdx.x * blockDim.x + threadIdx.x;
    if (i >= MTOT * DMODEL) return;
    int row = i / DMODEL, col = i - row * DMODEL;
    int b = row / STOK, s = row - b * STOK;
    float v = (s < NTOK) ? tmp[((size_t)b * NTOK + s) * DMODEL + col]
                         : cls[(size_t)(s - NTOK) * DMODEL + col];
    X[i] = v;
}

// ---------------------------------------------------------------------------
// LayerNorm over 768
// ---------------------------------------------------------------------------
__global__ __launch_bounds__(256) void ln768_kernel(
    const float* __restrict__ X, const float* __restrict__ g,
    const float* __restrict__ bb, float* __restrict__ Y)
{
    __shared__ float scr[8];
    int row = blockIdx.x, t = threadIdx.x;
    const float* x = X + (size_t)row * DMODEL;
    float v0 = x[t], v1 = x[t + 256], v2 = x[t + 512];
    float s  = block_reduce_sum(v0 + v1 + v2, scr);
    float sq = block_reduce_sum(v0 * v0 + v1 * v1 + v2 * v2, scr);
    float mean = s * (1.f / 768.f);
    float var  = sq * (1.f / 768.f) - mean * mean;
    float inv  = rsqrtf(var + LN_EPS);
    float* y = Y + (size_t)row * DMODEL;
    y[t]       = (v0 - mean) * inv * g[t]       + bb[t];
    y[t + 256] = (v1 - mean) * inv * g[t + 256] + bb[t + 256];
    y[t + 512] = (v2 - mean) * inv * g[t + 512] + bb[t + 512];
}

__global__ __launch_bounds__(256) void lndec_kernel(
    const float* __restrict__ X, const float* __restrict__ g,
    const float* __restrict__ bb, float* __restrict__ P, float* __restrict__ Cc)
{
    __shared__ float scr[8];
    int row = blockIdx.x, t = threadIdx.x;
    const float* x = X + (size_t)row * DMODEL;
    float v0 = x[t], v1 = x[t + 256], v2 = x[t + 512];
    float s  = block_reduce_sum(v0 + v1 + v2, scr);
    float sq = block_reduce_sum(v0 * v0 + v1 * v1 + v2 * v2, scr);
    float mean = s * (1.f / 768.f);
    float var  = sq * (1.f / 768.f) - mean * mean;
    float inv  = rsqrtf(var + LN_EPS);
    int b = row / STOK, sl = row - b * STOK;
    float* y = (sl < NTOK) ? P + ((size_t)b * NTOK + sl) * DMODEL
                           : Cc + ((size_t)b * NCLS + (sl - NTOK)) * DMODEL;
    y[t]       = (v0 - mean) * inv * g[t]       + bb[t];
    y[t + 256] = (v1 - mean) * inv * g[t + 256] + bb[t + 256];
    y[t + 512] = (v2 - mean) * inv * g[t + 512] + bb[t + 512];
}

__global__ __launch_bounds__(256) void l2n_kernel(const float* __restrict__ in,
                                                  float* __restrict__ out)
{
    __shared__ float scr[8];
    int row = blockIdx.x, t = threadIdx.x;
    const float* x = in + (size_t)row * DMODEL;
    float v0 = x[t], v1 = x[t + 256], v2 = x[t + 512];
    float sq = block_reduce_sum(v0 * v0 + v1 * v1 + v2 * v2, scr);
    float inv = rsqrtf(sq);
    float* y = out + (size_t)row * DMODEL;
    y[t] = v0 * inv; y[t + 256] = v1 * inv; y[t + 512] = v2 * inv;
}

__global__ void add_kernel(float* __restrict__ X, const float* __restrict__ O)
{
    int i = blockIdx.x * blockDim.x + threadIdx.x;
    float4 a = ((float4*)X)[i];
    float4 o = ((const float4*)O)[i];
    a.x += o.x; a.y += o.y; a.z += o.z; a.w += o.w;
    ((float4*)X)[i] = a;
}

// ---------------------------------------------------------------------------
// QKV block-diagonal projection
// ---------------------------------------------------------------------------
__global__ __launch_bounds__(256) void qkv_kernel(
    const float* __restrict__ Hb,
    const float* __restrict__ qW, const float* __restrict__ qb,
    const float* __restrict__ kW, const float* __restrict__ kb,
    const float* __restrict__ vW, const float* __restrict__ vb,
    int layer, float* __restrict__ Qo, float* __restrict__ Ko, float* __restrict__ Vo)
{
    __shared__ float Ws[64 * 64];
    __shared__ float Asm[64 * 65];
    int h = blockIdx.y, which = blockIdx.z;
    const float* W; const float* bias; float* Out;
    if (which == 0) { W = qW; bias = qb; Out = Qo; }
    else if (which == 1) { W = kW; bias = kb; Out = Ko; }
    else { W = vW; bias = vb; Out = Vo; }
    W    += ((size_t)layer * HEADS + h) * 4096;
    bias += ((size_t)layer * HEADS + h) * 64;
    int r0 = blockIdx.x * 64;
    int t = threadIdx.x;
    for (int i = t; i < 4096; i += 256) Ws[i] = W[i];
    for (int i = t; i < 4096; i += 256) {
        int r = i >> 6, d = i & 63;
        Asm[r * 65 + d] = (r0 + r < MTOT) ? Hb[(size_t)(r0 + r) * DMODEL + h * 64 + d] : 0.f;
    }
    __syncthreads();
    int tx = t & 15, ty = t >> 4;
    float acc[4][4];
#pragma unroll
    for (int i = 0; i < 4; i++)
#pragma unroll
        for (int j = 0; j < 4; j++) acc[i][j] = 0.f;
#pragma unroll 4
    for (int d = 0; d < 64; d++) {
        float a[4], w[4];
#pragma unroll
        for (int i = 0; i < 4; i++) a[i] = Asm[(ty * 4 + i) * 65 + d];
#pragma unroll
        for (int j = 0; j < 4; j++) w[j] = Ws[d * 64 + tx * 4 + j];
#pragma unroll
        for (int i = 0; i < 4; i++)
#pragma unroll
            for (int j = 0; j < 4; j++) acc[i][j] = fmaf(a[i], w[j], acc[i][j]);
    }
#pragma unroll
    for (int i = 0; i < 4; i++) {
        int r = r0 + ty * 4 + i;
        if (r >= MTOT) continue;
#pragma unroll
        for (int j = 0; j < 4; j++)
            Out[(size_t)r * DMODEL + h * 64 + tx * 4 + j] = acc[i][j] + bias[tx * 4 + j];
    }
}

// ---------------------------------------------------------------------------
// Attention (exact softmax, fp32)
// ---------------------------------------------------------------------------
#define QT 16
#define SPAD 1044
#define ATTN_SMEM ((QT*SPAD + QT*64 + 64*65)*4)

__global__ __launch_bounds__(256) void attn_kernel(
    const float* __restrict__ Q, const float* __restrict__ K,
    const float* __restrict__ V, float* __restrict__ O)
{
    extern __shared__ float sm[];
    float* sc = sm;
    float* qs = sm + QT * SPAD;
    float* kv = qs + QT * 64;
    int b = blockIdx.z, h = blockIdx.y;
    int q0 = blockIdx.x * QT;
    int t = threadIdx.x;
    size_t base = ((size_t)b * STOK) * DMODEL + h * 64;

    for (int i = t; i < QT * 64; i += 256) {
        int q = i >> 6, d = i & 63;
        qs[q * 64 + d] = (q0 + q < STOK) ? Q[base + (size_t)(q0 + q) * DMODEL + d] : 0.f;
    }
    __syncthreads();

    int kl  = t & 63;
    int qb4 = (t >> 6) << 2;
    for (int k0 = 0; k0 < STOK; k0 += 64) {
        for (int i = t; i < 4096; i += 256) {
            int r = i >> 6, d = i & 63;
            kv[r * 65 + d] = (k0 + r < STOK) ? K[base + (size_t)(k0 + r) * DMODEL + d] : 0.f;
        }
        __syncthreads();
        if (k0 + kl < STOK) {
            float a0 = 0.f, a1 = 0.f, a2 = 0.f, a3 = 0.f;
#pragma unroll 8
            for (int d = 0; d < 64; d++) {
                float kv_ = kv[kl * 65 + d];
                a0 = fmaf(qs[(qb4 + 0) * 64 + d], kv_, a0);
                a1 = fmaf(qs[(qb4 + 1) * 64 + d], kv_, a1);
                a2 = fmaf(qs[(qb4 + 2) * 64 + d], kv_, a2);
                a3 = fmaf(qs[(qb4 + 3) * 64 + d], kv_, a3);
            }
            int kc = k0 + kl;
            sc[(qb4 + 0) * SPAD + kc] = a0 * 0.125f;
            sc[(qb4 + 1) * SPAD + kc] = a1 * 0.125f;
            sc[(qb4 + 2) * SPAD + kc] = a2 * 0.125f;
            sc[(qb4 + 3) * SPAD + kc] = a3 * 0.125f;
        }
        __syncthreads();
    }

    int w = t >> 5, lane = t & 31;
    for (int q = w; q < QT; q += 8) {
        if (q0 + q >= STOK) continue;
        float mx = -1e30f;
        for (int k = lane; k < STOK; k += 32) mx = fmaxf(mx, sc[q * SPAD + k]);
#pragma unroll
        for (int o = 16; o; o >>= 1) mx = fmaxf(mx, __shfl_xor_sync(0xffffffffu, mx, o));
        float s = 0.f;
        for (int k = lane; k < STOK; k += 32) {
            float e = __expf(sc[q * SPAD + k] - mx);
            sc[q * SPAD + k] = e;
            s += e;
        }
#pragma unroll
        for (int o = 16; o; o >>= 1) s += __shfl_xor_sync(0xffffffffu, s, o);
        float inv = 1.f / s;
        for (int k = lane; k < STOK; k += 32) sc[q * SPAD + k] *= inv;
    }
    __syncthreads();

    int qv = t >> 4;
    int dd = (t & 15) << 2;
    float o0 = 0.f, o1 = 0.f, o2 = 0.f, o3 = 0.f;
    for (int k0 = 0; k0 < STOK; k0 += 64) {
        for (int i = t; i < 4096; i += 256) {
            int r = i >> 6, d = i & 63;
            kv[r * 65 + d] = (k0 + r < STOK) ? V[base + (size_t)(k0 + r) * DMODEL + d] : 0.f;
        }
        __syncthreads();
        int kmax = min(64, STOK - k0);
        for (int kk = 0; kk < kmax; kk++) {
            float p = sc[qv * SPAD + k0 + kk];
            o0 = fmaf(p, kv[kk * 65 + dd + 0], o0);
            o1 = fmaf(p, kv[kk * 65 + dd + 1], o1);
            o2 = fmaf(p, kv[kk * 65 + dd + 2], o2);
            o3 = fmaf(p, kv[kk * 65 + dd + 3], o3);
        }
        __syncthreads();
    }
    if (q0 + qv < STOK) {
        float* op = O + base + (size_t)(q0 + qv) * DMODEL + dd;
        op[0] = o0; op[1] = o1; op[2] = o2; op[3] = o3;
    }
}

// ---------------------------------------------------------------------------
// Cosine-sim mask logits + mask LayerNorm -> (b, c, n)
// ---------------------------------------------------------------------------
__global__ __launch_bounds__(256) void classdot_ln_kernel(
    const float* __restrict__ pp, const float* __restrict__ cn,
    const float* __restrict__ mg, const float* __restrict__ mb,
    float* __restrict__ ms)
{
    __shared__ float p[768];
    __shared__ float dots[32];
    __shared__ float mv[2];
    __shared__ float scr[8];
    int n = blockIdx.x, b = blockIdx.y;
    int t = threadIdx.x;
    const float* prow = pp + ((size_t)b * NTOK + n) * DMODEL;
    float a0 = prow[t], a1 = prow[t + 256], a2 = prow[t + 512];
    p[t] = a0; p[t + 256] = a1; p[t + 512] = a2;
    float sq = block_reduce_sum(a0 * a0 + a1 * a1 + a2 * a2, scr);
    float pinv = rsqrtf(sq);
    __syncthreads();
    int w = t >> 5, lane = t & 31;
    for (int c = w; c < NCLS; c += 8) {
        const float* crow = cn + ((size_t)b * NCLS + c) * DMODEL;
        float s = 0.f;
        for (int d = lane; d < DMODEL; d += 32) s += p[d] * crow[d];
#pragma unroll
        for (int o = 16; o; o >>= 1) s += __shfl_xor_sync(0xffffffffu, s, o);
        if (!lane) dots[c] = s * pinv;
    }
    __syncthreads();
    if (t == 0) {
        float m = 0.f;
        for (int c = 0; c < NCLS; c++) m += dots[c];
        m *= (1.f / NCLS);
        float v = 0.f;
        for (int c = 0; c < NCLS; c++) { float d = dots[c] - m; v += d * d; }
        v *= (1.f / NCLS);
        mv[0] = m; mv[1] = rsqrtf(v + LN_EPS);
    }
    __syncthreads();
    if (t < NCLS)
        ms[((size_t)b * NCLS + t) * NTOK + n] = (dots[t] - mv[0]) * mv[1] * mg[t] + mb[t];
}

// ---------------------------------------------------------------------------
// Bilinear 32x32 -> 512x512
// ---------------------------------------------------------------------------
__global__ void resize_kernel(const float* __restrict__ ms, float* __restrict__ out)
{
    int i = blockIdx.x * blockDim.x + threadIdx.x;
    int xq = i & 127;
    int r  = i >> 7;
    int oy = r & 511; r >>= 9;
    int c  = r % NCLS;
    int b  = r / NCLS;
    const float* m = ms + ((size_t)b * NCLS + c) * NTOK;

    float fy = oy * 0.0625f - 0.46875f;
    float fyf = floorf(fy);
    float wy = fy - fyf;
    int y0 = (int)fyf, y1 = y0 + 1;
    y0 = max(0, min(31, y0));
    y1 = max(0, min(31, y1));
    const float* r0p = m + y0 * 32;
    const float* r1p = m + y1 * 32;

    float4 o4;
    float* po = (float*)&o4;
    int ox0 = xq * 4;
#pragma unroll
    for (int j = 0; j < 4; j++) {
        float fx = (ox0 + j) * 0.0625f - 0.46875f;
        float fxf = floorf(fx);
        float wx = fx - fxf;
        int x0 = (int)fxf, x1 = x0 + 1;
        x0 = max(0, min(31, x0));
        x1 = max(0, min(31, x1));
        float top = (1.f - wx) * r0p[x0] + wx * r0p[x1];
        float bot = (1.f - wx) * r1p[x0] + wx * r1p[x1];
        po[j] = (1.f - wy) * top + wy * bot;
    }
    *(float4*)(out + (((size_t)b * NCLS + c) * IMG + oy) * IMG + ox0) = o4;
}

// ---------------------------------------------------------------------------
// Host launcher
// ---------------------------------------------------------------------------
extern "C" void kernel_launch(void* const* d_in, const int* in_sizes, int n_in,
                              void* d_out, int out_size)
{
    const float* x          = (const float*)d_in[0];
    const float* proj_dec_W = (const float*)d_in[1];
    const float* proj_dec_b = (const float*)d_in[2];
    const float* cls_emb    = (const float*)d_in[3];
    const float* ln1_g      = (const float*)d_in[4];
    const float* ln1_b      = (const float*)d_in[5];
    const float* qW         = (const float*)d_in[6];
    const float* qb         = (const float*)d_in[7];
    const float* kW         = (const float*)d_in[8];
    const float* kb         = (const float*)d_in[9];
    const float* vW         = (const float*)d_in[10];
    const float* vb         = (const float*)d_in[11];
    const float* ln2_g      = (const float*)d_in[12];
    const float* ln2_b      = (const float*)d_in[13];
    const float* mlp_W1     = (const float*)d_in[14];
    const float* mlp_b1     = (const float*)d_in[15];
    const float* mlp_W2     = (const float*)d_in[16];
    const float* mlp_b2     = (const float*)d_in[17];
    const float* proj_patch = (const float*)d_in[18];
    const float* proj_cls   = (const float*)d_in[19];
    const float* dec_g      = (const float*)d_in[20];
    const float* dec_b      = (const float*)d_in[21];
    const float* mask_g     = (const float*)d_in[22];
    const float* mask_b     = (const float*)d_in[23];
    float* out = (float*)d_out;

    float *pTmp, *pX, *pH, *pQ, *pK, *pV, *pO, *pM1, *pPln, *pPP, *pCln, *pCP, *pCN, *pMS;
    cudaGetSymbolAddress((void**)&pTmp, g_Tmp);
    cudaGetSymbolAddress((void**)&pX,   g_X);
    cudaGetSymbolAddress((void**)&pH,   g_H);
    cudaGetSymbolAddress((void**)&pQ,   g_Q);
    cudaGetSymbolAddress((void**)&pK,   g_K);
    cudaGetSymbolAddress((void**)&pV,   g_V);
    cudaGetSymbolAddress((void**)&pO,   g_O);
    cudaGetSymbolAddress((void**)&pM1,  g_M1);
    cudaGetSymbolAddress((void**)&pPln, g_Pln);
    cudaGetSymbolAddress((void**)&pPP,  g_PP);
    cudaGetSymbolAddress((void**)&pCln, g_Cln);
    cudaGetSymbolAddress((void**)&pCP,  g_CP);
    cudaGetSymbolAddress((void**)&pCN,  g_CN);
    cudaGetSymbolAddress((void**)&pMS,  g_MS);

    cudaFuncSetAttribute(attn_kernel, cudaFuncAttributeMaxDynamicSharedMemorySize, ATTN_SMEM);
    cudaFuncSetAttribute(gemm_tf32x3, cudaFuncAttributeMaxDynamicSharedMemorySize, GEMM_SMEM);

    // 1) proj_dec: Tmp = x @ W + b
    gemm_tf32x3<<<dim3(6, 64), 256, GEMM_SMEM>>>(x, DMODEL, proj_dec_W, DMODEL, proj_dec_b,
                                                 pTmp, DMODEL, BATCH * NTOK, DMODEL, DMODEL, 0);
    // 2) assemble
    assemble_kernel<<<(MTOT * DMODEL + 255) / 256, 256>>>(pTmp, cls_emb, pX);

    for (int l = 0; l < LAYERS; l++) {
        ln768_kernel<<<MTOT, 256>>>(pX, ln1_g + l * DMODEL, ln1_b + l * DMODEL, pH);
        qkv_kernel<<<dim3((MTOT + 63) / 64, HEADS, 3), 256>>>(
            pH, qW, qb, kW, kb, vW, vb, l, pQ, pK, pV);
        attn_kernel<<<dim3((STOK + QT - 1) / QT, HEADS, BATCH), 256, ATTN_SMEM>>>(pQ, pK, pV, pO);
        add_kernel<<<MTOT * DMODEL / 4 / 256, 256>>>(pX, pO);
        ln768_kernel<<<MTOT, 256>>>(pX, ln2_g + l * DMODEL, ln2_b + l * DMODEL, pH);
        gemm_tf32x3<<<dim3(24, (MTOT + 127) / 128), 256, GEMM_SMEM>>>(
            pH, DMODEL, mlp_W1 + (size_t)l * DMODEL * DMLP, DMLP, mlp_b1 + l * DMLP,
            pM1, DMLP, MTOT, DMLP, DMODEL, 1 /*gelu*/);
        gemm_tf32x3<<<dim3(6, (MTOT + 127) / 128), 256, GEMM_SMEM>>>(
            pM1, DMLP, mlp_W2 + (size_t)l * DMLP * DMODEL, DMODEL, mlp_b2 + l * DMODEL,
            pX, DMODEL, MTOT, DMODEL, DMLP, 2 /*accumulate*/);
    }

    lndec_kernel<<<MTOT, 256>>>(pX, dec_g, dec_b, pPln, pCln);
    gemm_tf32x3<<<dim3(6, 64), 256, GEMM_SMEM>>>(pPln, DMODEL, proj_patch, DMODEL, nullptr,
                                                 pPP, DMODEL, BATCH * NTOK, DMODEL, DMODEL, 0);
    gemm_tf32x3<<<dim3(6, 2), 256, GEMM_SMEM>>>(pCln, DMODEL, proj_cls, DMODEL, nullptr,
                                                pCP, DMODEL, BATCH * NCLS, DMODEL, DMODEL, 0);
    l2n_kernel<<<BATCH * NCLS, 256>>>(pCP, pCN);
    classdot_ln_kernel<<<dim3(NTOK, BATCH), 256>>>(pPP, pCN, mask_g, mask_b, pMS);
    resize_kernel<<<BATCH * NCLS * IMG * (IMG / 4) / 256, 256>>>(pMS, out);
}

// round 5
// speedup vs baseline: 1.5109x; 1.3773x over previous
#include <cuda_runtime.h>
#include <stdint.h>
#include <math.h>

// ---------------------------------------------------------------------------
// MaskTransformer: fixed shapes
// ---------------------------------------------------------------------------
#define LAYERS 2
#define HEADS  12
#define DMODEL 768
#define DHEAD  64
#define BATCH  8
#define NTOK   1024
#define NCLS   19
#define STOK   1043                 // NTOK + NCLS
#define MTOT   (BATCH*STOK)         // 8344
#define DMLP   3072
#define IMG    512
#define LN_EPS 1e-5f

// ---------------------------------------------------------------------------
// Scratch buffers
// ---------------------------------------------------------------------------
__device__ float g_Tmp[BATCH*NTOK*DMODEL];
__device__ float g_X  [MTOT*DMODEL];
__device__ float g_H  [MTOT*DMODEL];
__device__ float g_Q  [MTOT*DMODEL];
__device__ float g_K  [MTOT*DMODEL];
__device__ float g_V  [MTOT*DMODEL];
__device__ float g_O  [MTOT*DMODEL];
__device__ float g_M1 [MTOT*DMLP];
__device__ float g_Pln[BATCH*NTOK*DMODEL];
__device__ float g_PP [BATCH*NTOK*DMODEL];
__device__ float g_Cln[BATCH*NCLS*DMODEL];
__device__ float g_CP [BATCH*NCLS*DMODEL];
__device__ float g_CN [BATCH*NCLS*DMODEL];
__device__ float g_MS [BATCH*NCLS*NTOK];

// ---------------------------------------------------------------------------
// helpers
// ---------------------------------------------------------------------------
__device__ __forceinline__ float block_reduce_sum(float v, float* scratch) {
    int lane = threadIdx.x & 31, w = threadIdx.x >> 5;
#pragma unroll
    for (int o = 16; o; o >>= 1) v += __shfl_xor_sync(0xffffffffu, v, o);
    if (!lane) scratch[w] = v;
    __syncthreads();
    float r = (threadIdx.x < 8) ? scratch[threadIdx.x] : 0.f;
    if (w == 0) {
#pragma unroll
        for (int o = 4; o; o >>= 1) r += __shfl_xor_sync(0xffffffffu, r, o);
        if (!lane) scratch[0] = r;
    }
    __syncthreads();
    r = scratch[0];
    __syncthreads();
    return r;
}

__device__ __forceinline__ uint32_t tf32_rna(float f) {
    uint32_t u;
    asm("cvt.rna.tf32.f32 %0, %1;" : "=r"(u) : "f"(f));
    return u;
}

__device__ __forceinline__ void mma_tf32(float* c, const uint32_t* a, const uint32_t* b) {
    asm volatile(
        "mma.sync.aligned.m16n8k8.row.col.f32.tf32.tf32.f32 "
        "{%0,%1,%2,%3}, {%4,%5,%6,%7}, {%8,%9}, {%0,%1,%2,%3};"
        : "+f"(c[0]), "+f"(c[1]), "+f"(c[2]), "+f"(c[3])
        : "r"(a[0]), "r"(a[1]), "r"(a[2]), "r"(a[3]), "r"(b[0]), "r"(b[1]));
}

// ---------------------------------------------------------------------------
// TF32x3 tensor-core GEMM (identical to the R2 kernel that PASSED)
// ---------------------------------------------------------------------------
#define SPITCH 136
#define AS(k,m) ((k)*SPITCH + (m))
#define GEMM_SMEM (4*32*SPITCH*4)

__global__ __launch_bounds__(256) void gemm_tf32x3(
    const float* __restrict__ A, int lda,
    const float* __restrict__ B, int ldb,
    const float* __restrict__ bias,
    float* __restrict__ C, int ldc,
    int M, int N, int K, int flags)
{
    extern __shared__ uint32_t sh[];
    uint32_t* sAh = sh;
    uint32_t* sAl = sAh + 32 * SPITCH;
    uint32_t* sBh = sAl + 32 * SPITCH;
    uint32_t* sBl = sBh + 32 * SPITCH;

    int tid = threadIdx.x, wid = tid >> 5, lane = tid & 31;
    int g = lane >> 2, t = lane & 3;
    int wm = (wid & 3) * 32, wn = (wid >> 2) * 64;
    int row0 = blockIdx.y * 128, col0 = blockIdx.x * 128;

    float acc[2][8][4];
#pragma unroll
    for (int i = 0; i < 2; i++)
#pragma unroll
        for (int j = 0; j < 8; j++)
#pragma unroll
            for (int q = 0; q < 4; q++) acc[i][j][q] = 0.f;

    int m_l = tid & 127, kgA = (tid >> 7) * 16;
    int k_lb = tid >> 3, n_lb = (tid & 7) * 16;

    float4 apf[4], bpf[4];

    auto g_load = [&](int kt) {
        int ar = row0 + m_l;
        if (ar < M) {
            const float* Ap = A + (size_t)ar * lda + kt + kgA;
#pragma unroll
            for (int i = 0; i < 4; i++) apf[i] = *(const float4*)(Ap + 4 * i);
        } else {
#pragma unroll
            for (int i = 0; i < 4; i++) apf[i] = make_float4(0.f, 0.f, 0.f, 0.f);
        }
        const float* Bp = B + (size_t)(kt + k_lb) * ldb + col0 + n_lb;
#pragma unroll
        for (int i = 0; i < 4; i++) bpf[i] = *(const float4*)(Bp + 4 * i);
    };

    auto s_store = [&]() {
#pragma unroll
        for (int i = 0; i < 4; i++) {
            const float* v = (const float*)&apf[i];
#pragma unroll
            for (int j = 0; j < 4; j++) {
                float x = v[j];
                uint32_t h = tf32_rna(x);
                float r = x - __uint_as_float(h);
                int idx = AS(kgA + 4 * i + j, m_l);
                sAh[idx] = h;
                sAl[idx] = tf32_rna(r);
            }
        }
#pragma unroll
        for (int i = 0; i < 4; i++) {
            const float* v = (const float*)&bpf[i];
#pragma unroll
            for (int j = 0; j < 4; j++) {
                float x = v[j];
                uint32_t h = tf32_rna(x);
                float r = x - __uint_as_float(h);
                int idx = AS(k_lb, n_lb + 4 * i + j);
                sBh[idx] = h;
                sBl[idx] = tf32_rna(r);
            }
        }
    };

    auto compute = [&]() {
#pragma unroll
        for (int ks = 0; ks < 4; ks++) {
            int kb = ks * 8;
            uint32_t ah[2][4], al[2][4];
#pragma unroll
            for (int mt = 0; mt < 2; mt++) {
                int r = wm + mt * 16 + g;
                ah[mt][0] = sAh[AS(kb + t,     r)];
                ah[mt][1] = sAh[AS(kb + t,     r + 8)];
                ah[mt][2] = sAh[AS(kb + t + 4, r)];
                ah[mt][3] = sAh[AS(kb + t + 4, r + 8)];
                al[mt][0] = sAl[AS(kb + t,     r)];
                al[mt][1] = sAl[AS(kb + t,     r + 8)];
                al[mt][2] = sAl[AS(kb + t + 4, r)];
                al[mt][3] = sAl[AS(kb + t + 4, r + 8)];
            }
#pragma unroll
            for (int nt = 0; nt < 8; nt++) {
                int c = wn + nt * 8 + g;
                uint32_t bh[2], bl[2];
                bh[0] = sBh[AS(kb + t,     c)];
                bh[1] = sBh[AS(kb + t + 4, c)];
                bl[0] = sBl[AS(kb + t,     c)];
                bl[1] = sBl[AS(kb + t + 4, c)];
#pragma unroll
                for (int mt = 0; mt < 2; mt++) {
                    mma_tf32(acc[mt][nt], al[mt], bh);
                    mma_tf32(acc[mt][nt], ah[mt], bl);
                    mma_tf32(acc[mt][nt], ah[mt], bh);
                }
            }
        }
    };

    g_load(0);
    s_store();
    __syncthreads();
    for (int kt = 0; kt < K; kt += 32) {
        bool more = (kt + 32) < K;
        if (more) g_load(kt + 32);
        compute();
        __syncthreads();
        if (more) { s_store(); __syncthreads(); }
    }

#pragma unroll
    for (int mt = 0; mt < 2; mt++) {
#pragma unroll
        for (int nt = 0; nt < 8; nt++) {
            int c = col0 + wn + nt * 8 + 2 * t;
#pragma unroll
            for (int half = 0; half < 2; half++) {
                int r = row0 + wm + mt * 16 + g + half * 8;
                if (r >= M) continue;
                float v0 = acc[mt][nt][half * 2 + 0];
                float v1 = acc[mt][nt][half * 2 + 1];
                if (bias) { v0 += bias[c]; v1 += bias[c + 1]; }
                if (flags & 1) {
                    v0 = 0.5f * v0 * (1.f + erff(v0 * 0.70710678118654752f));
                    v1 = 0.5f * v1 * (1.f + erff(v1 * 0.70710678118654752f));
                }
                float* p = C + (size_t)r * ldc + c;
                if (flags & 2) { v0 += p[0]; v1 += p[1]; }
                p[0] = v0; p[1] = v1;
            }
        }
    }
}

// ---------------------------------------------------------------------------
// Assemble X = concat(proj_dec(x), cls_emb broadcast)
// ---------------------------------------------------------------------------
__global__ void assemble_kernel(const float* __restrict__ tmp,
                                const float* __restrict__ cls,
                                float* __restrict__ X)
{
    int i = blockIdx.x * blockDim.x + threadIdx.x;
    if (i >= MTOT * DMODEL) return;
    int row = i / DMODEL, col = i - row * DMODEL;
    int b = row / STOK, s = row - b * STOK;
    float v = (s < NTOK) ? tmp[((size_t)b * NTOK + s) * DMODEL + col]
                         : cls[(size_t)(s - NTOK) * DMODEL + col];
    X[i] = v;
}

// ---------------------------------------------------------------------------
// LayerNorm over 768 (plain + fused-residual variants)
// ---------------------------------------------------------------------------
__global__ __launch_bounds__(256) void ln768_kernel(
    const float* __restrict__ X, const float* __restrict__ g,
    const float* __restrict__ bb, float* __restrict__ Y)
{
    __shared__ float scr[8];
    int row = blockIdx.x, t = threadIdx.x;
    const float* x = X + (size_t)row * DMODEL;
    float v0 = x[t], v1 = x[t + 256], v2 = x[t + 512];
    float s  = block_reduce_sum(v0 + v1 + v2, scr);
    float sq = block_reduce_sum(v0 * v0 + v1 * v1 + v2 * v2, scr);
    float mean = s * (1.f / 768.f);
    float var  = sq * (1.f / 768.f) - mean * mean;
    float inv  = rsqrtf(var + LN_EPS);
    float* y = Y + (size_t)row * DMODEL;
    y[t]       = (v0 - mean) * inv * g[t]       + bb[t];
    y[t + 256] = (v1 - mean) * inv * g[t + 256] + bb[t + 256];
    y[t + 512] = (v2 - mean) * inv * g[t + 512] + bb[t + 512];
}

// X += O, then H = LN(X)
__global__ __launch_bounds__(256) void ln768_addres_kernel(
    float* __restrict__ X, const float* __restrict__ O,
    const float* __restrict__ g, const float* __restrict__ bb,
    float* __restrict__ Y)
{
    __shared__ float scr[8];
    int row = blockIdx.x, t = threadIdx.x;
    float* x = X + (size_t)row * DMODEL;
    const float* o = O + (size_t)row * DMODEL;
    float v0 = x[t] + o[t], v1 = x[t + 256] + o[t + 256], v2 = x[t + 512] + o[t + 512];
    x[t] = v0; x[t + 256] = v1; x[t + 512] = v2;
    float s  = block_reduce_sum(v0 + v1 + v2, scr);
    float sq = block_reduce_sum(v0 * v0 + v1 * v1 + v2 * v2, scr);
    float mean = s * (1.f / 768.f);
    float var  = sq * (1.f / 768.f) - mean * mean;
    float inv  = rsqrtf(var + LN_EPS);
    float* y = Y + (size_t)row * DMODEL;
    y[t]       = (v0 - mean) * inv * g[t]       + bb[t];
    y[t + 256] = (v1 - mean) * inv * g[t + 256] + bb[t + 256];
    y[t + 512] = (v2 - mean) * inv * g[t + 512] + bb[t + 512];
}

__global__ __launch_bounds__(256) void lndec_kernel(
    const float* __restrict__ X, const float* __restrict__ g,
    const float* __restrict__ bb, float* __restrict__ P, float* __restrict__ Cc)
{
    __shared__ float scr[8];
    int row = blockIdx.x, t = threadIdx.x;
    const float* x = X + (size_t)row * DMODEL;
    float v0 = x[t], v1 = x[t + 256], v2 = x[t + 512];
    float s  = block_reduce_sum(v0 + v1 + v2, scr);
    float sq = block_reduce_sum(v0 * v0 + v1 * v1 + v2 * v2, scr);
    float mean = s * (1.f / 768.f);
    float var  = sq * (1.f / 768.f) - mean * mean;
    float inv  = rsqrtf(var + LN_EPS);
    int b = row / STOK, sl = row - b * STOK;
    float* y = (sl < NTOK) ? P + ((size_t)b * NTOK + sl) * DMODEL
                           : Cc + ((size_t)b * NCLS + (sl - NTOK)) * DMODEL;
    y[t]       = (v0 - mean) * inv * g[t]       + bb[t];
    y[t + 256] = (v1 - mean) * inv * g[t + 256] + bb[t + 256];
    y[t + 512] = (v2 - mean) * inv * g[t + 512] + bb[t + 512];
}

__global__ __launch_bounds__(256) void l2n_kernel(const float* __restrict__ in,
                                                  float* __restrict__ out)
{
    __shared__ float scr[8];
    int row = blockIdx.x, t = threadIdx.x;
    const float* x = in + (size_t)row * DMODEL;
    float v0 = x[t], v1 = x[t + 256], v2 = x[t + 512];
    float sq = block_reduce_sum(v0 * v0 + v1 * v1 + v2 * v2, scr);
    float inv = rsqrtf(sq);
    float* y = out + (size_t)row * DMODEL;
    y[t] = v0 * inv; y[t + 256] = v1 * inv; y[t + 512] = v2 * inv;
}

// ---------------------------------------------------------------------------
// QKV block-diagonal projection
// ---------------------------------------------------------------------------
__global__ __launch_bounds__(256) void qkv_kernel(
    const float* __restrict__ Hb,
    const float* __restrict__ qW, const float* __restrict__ qb,
    const float* __restrict__ kW, const float* __restrict__ kb,
    const float* __restrict__ vW, const float* __restrict__ vb,
    int layer, float* __restrict__ Qo, float* __restrict__ Ko, float* __restrict__ Vo)
{
    __shared__ float Ws[64 * 64];
    __shared__ float Asm[64 * 65];
    int h = blockIdx.y, which = blockIdx.z;
    const float* W; const float* bias; float* Out;
    if (which == 0) { W = qW; bias = qb; Out = Qo; }
    else if (which == 1) { W = kW; bias = kb; Out = Ko; }
    else { W = vW; bias = vb; Out = Vo; }
    W    += ((size_t)layer * HEADS + h) * 4096;
    bias += ((size_t)layer * HEADS + h) * 64;
    int r0 = blockIdx.x * 64;
    int t = threadIdx.x;
    for (int i = t; i < 4096; i += 256) Ws[i] = W[i];
    for (int i = t; i < 4096; i += 256) {
        int r = i >> 6, d = i & 63;
        Asm[r * 65 + d] = (r0 + r < MTOT) ? Hb[(size_t)(r0 + r) * DMODEL + h * 64 + d] : 0.f;
    }
    __syncthreads();
    int tx = t & 15, ty = t >> 4;
    float acc[4][4];
#pragma unroll
    for (int i = 0; i < 4; i++)
#pragma unroll
        for (int j = 0; j < 4; j++) acc[i][j] = 0.f;
#pragma unroll 4
    for (int d = 0; d < 64; d++) {
        float a[4], w[4];
#pragma unroll
        for (int i = 0; i < 4; i++) a[i] = Asm[(ty * 4 + i) * 65 + d];
#pragma unroll
        for (int j = 0; j < 4; j++) w[j] = Ws[d * 64 + tx * 4 + j];
#pragma unroll
        for (int i = 0; i < 4; i++)
#pragma unroll
            for (int j = 0; j < 4; j++) acc[i][j] = fmaf(a[i], w[j], acc[i][j]);
    }
#pragma unroll
    for (int i = 0; i < 4; i++) {
        int r = r0 + ty * 4 + i;
        if (r >= MTOT) continue;
#pragma unroll
        for (int j = 0; j < 4; j++)
            Out[(size_t)r * DMODEL + h * 64 + tx * 4 + j] = acc[i][j] + bias[tx * 4 + j];
    }
}

// ---------------------------------------------------------------------------
// Tensor-core attention (tf32x3), two-pass exact softmax.
// Block = (32-query tile, head, batch), 256 threads = 8 warps.
// K/V chunks stored as raw fp32 in SMEM; hi/lo tf32 split at fragment load.
// SMEM: 32*1092 (scores) + 64*68 (chunk) floats = 157,184 B.
// ---------------------------------------------------------------------------
#define AQT   32
#define ASPAD 1092      // ≡ 4 (mod 32): conflict-free fragment loads
#define NCHUNK 17       // ceil(1043/64)
#define KPITCH 68       // K chunk [key][d]
#define VPITCH 66       // V chunk [d][key]
#define ATTN_WORDS (AQT*ASPAD + 64*KPITCH)
#define ATTN_SMEM  (ATTN_WORDS*4)

__global__ __launch_bounds__(256) void attn_mma_kernel(
    const float* __restrict__ Q, const float* __restrict__ K,
    const float* __restrict__ V, float* __restrict__ O)
{
    extern __shared__ float sm[];
    float* sc   = sm;                   // 32 x 1092 scores
    float* buff = sm + AQT * ASPAD;     // 64*68 chunk buffer (fp32)

    int b = blockIdx.z, h = blockIdx.y;
    int q0 = blockIdx.x * AQT;
    int tid = threadIdx.x, wid = tid >> 5, lane = tid & 31;
    int g = lane >> 2, t = lane & 3;
    int wm = (wid & 1) * 16;          // query sub-tile
    int wq = (wid >> 1) * 16;         // QK: key offset in chunk; PV: d offset
    size_t base = (size_t)b * STOK * DMODEL + h * 64;

    // ---- load Q fragments into registers (persist across all chunks) ----
    uint32_t aqh[8][4], aql[8][4];
    {
        int r1 = q0 + wm + g, r2 = r1 + 8;
        const float* Q1 = Q + base + (size_t)r1 * DMODEL;
        const float* Q2 = Q + base + (size_t)r2 * DMODEL;
        bool ok1 = r1 < STOK, ok2 = r2 < STOK;
#pragma unroll
        for (int ks = 0; ks < 8; ks++) {
            int d = ks * 8 + t;
            float x0 = ok1 ? Q1[d]     : 0.f;
            float x1 = ok2 ? Q2[d]     : 0.f;
            float x2 = ok1 ? Q1[d + 4] : 0.f;
            float x3 = ok2 ? Q2[d + 4] : 0.f;
            aqh[ks][0] = tf32_rna(x0); aql[ks][0] = tf32_rna(x0 - __uint_as_float(aqh[ks][0]));
            aqh[ks][1] = tf32_rna(x1); aql[ks][1] = tf32_rna(x1 - __uint_as_float(aqh[ks][1]));
            aqh[ks][2] = tf32_rna(x2); aql[ks][2] = tf32_rna(x2 - __uint_as_float(aqh[ks][2]));
            aqh[ks][3] = tf32_rna(x3); aql[ks][3] = tf32_rna(x3 - __uint_as_float(aqh[ks][3]));
        }
    }

    // ---- Phase 1: S = Q K^T / 8 ----
    for (int c = 0; c < NCHUNK; c++) {
        int k0 = c * 64;
        __syncthreads();
        // load K chunk [key][d] as fp32, zero-pad beyond STOK
#pragma unroll
        for (int j = 0; j < 4; j++) {
            int key = (tid >> 4) + j * 16;
            int d4 = (tid & 15) * 4;
            int gk = k0 + key;
            float4 v = make_float4(0.f, 0.f, 0.f, 0.f);
            if (gk < STOK) v = *(const float4*)(K + base + (size_t)gk * DMODEL + d4);
            *(float4*)&buff[key * KPITCH + d4] = v;
        }
        __syncthreads();
#pragma unroll
        for (int nt = 0; nt < 2; nt++) {
            int nb = (wq + nt * 8 + g) * KPITCH;
            float acc[4] = {0.f, 0.f, 0.f, 0.f};
#pragma unroll
            for (int ks = 0; ks < 8; ks++) {
                int dd = ks * 8 + t;
                float f0 = buff[nb + dd];
                float f1 = buff[nb + dd + 4];
                uint32_t bh[2], bl[2];
                bh[0] = tf32_rna(f0); bl[0] = tf32_rna(f0 - __uint_as_float(bh[0]));
                bh[1] = tf32_rna(f1); bl[1] = tf32_rna(f1 - __uint_as_float(bh[1]));
                mma_tf32(acc, aql[ks], bh);
                mma_tf32(acc, aqh[ks], bl);
                mma_tf32(acc, aqh[ks], bh);
            }
            int col = k0 + wq + nt * 8 + 2 * t;
            *(float2*)&sc[(wm + g) * ASPAD + col]     = make_float2(acc[0] * 0.125f, acc[1] * 0.125f);
            *(float2*)&sc[(wm + g + 8) * ASPAD + col] = make_float2(acc[2] * 0.125f, acc[3] * 0.125f);
        }
    }
    __syncthreads();

    // ---- Phase 2: row softmax (exact, keys < STOK) ----
#pragma unroll
    for (int rr = 0; rr < 4; rr++) {
        int q = wid * 4 + rr;
        float* row = sc + q * ASPAD;
        float mx = -1e30f;
        for (int k = lane; k < STOK; k += 32) mx = fmaxf(mx, row[k]);
#pragma unroll
        for (int o = 16; o; o >>= 1) mx = fmaxf(mx, __shfl_xor_sync(0xffffffffu, mx, o));
        float s = 0.f;
        for (int k = lane; k < STOK; k += 32) {
            float e = __expf(row[k] - mx);
            row[k] = e;
            s += e;
        }
#pragma unroll
        for (int o = 16; o; o >>= 1) s += __shfl_xor_sync(0xffffffffu, s, o);
        float inv = 1.f / s;
        for (int k = lane; k < STOK; k += 32) row[k] *= inv;
    }

    // ---- Phase 3: O = P V ----
    float oacc[2][4];
#pragma unroll
    for (int i = 0; i < 2; i++)
#pragma unroll
        for (int j = 0; j < 4; j++) oacc[i][j] = 0.f;

    for (int c = 0; c < NCHUNK; c++) {
        int k0 = c * 64;
        __syncthreads();
        // load V chunk transposed [d][key] as fp32, zero-pad
#pragma unroll
        for (int j = 0; j < 4; j++) {
            int key = tid & 63;
            int d4 = (tid >> 6) * 4 + j * 16;
            int gk = k0 + key;
            float4 v = make_float4(0.f, 0.f, 0.f, 0.f);
            if (gk < STOK) v = *(const float4*)(V + base + (size_t)gk * DMODEL + d4);
            const float* vp = (const float*)&v;
#pragma unroll
            for (int jj = 0; jj < 4; jj++)
                buff[(d4 + jj) * VPITCH + key] = vp[jj];
        }
        __syncthreads();
#pragma unroll
        for (int ks = 0; ks < 8; ks++) {
            int kk = ks * 8;
            float p0 = sc[(wm + g) * ASPAD + k0 + kk + t];
            float p1 = sc[(wm + g + 8) * ASPAD + k0 + kk + t];
            float p2 = sc[(wm + g) * ASPAD + k0 + kk + t + 4];
            float p3 = sc[(wm + g + 8) * ASPAD + k0 + kk + t + 4];
            uint32_t ah[4], al[4];
            ah[0] = tf32_rna(p0); al[0] = tf32_rna(p0 - __uint_as_float(ah[0]));
            ah[1] = tf32_rna(p1); al[1] = tf32_rna(p1 - __uint_as_float(ah[1]));
            ah[2] = tf32_rna(p2); al[2] = tf32_rna(p2 - __uint_as_float(ah[2]));
            ah[3] = tf32_rna(p3); al[3] = tf32_rna(p3 - __uint_as_float(ah[3]));
#pragma unroll
            for (int nt = 0; nt < 2; nt++) {
                int dn = (wq + nt * 8 + g) * VPITCH + kk;
                float f0 = buff[dn + t];
                float f1 = buff[dn + t + 4];
                uint32_t bh[2], bl[2];
                bh[0] = tf32_rna(f0); bl[0] = tf32_rna(f0 - __uint_as_float(bh[0]));
                bh[1] = tf32_rna(f1); bl[1] = tf32_rna(f1 - __uint_as_float(bh[1]));
                mma_tf32(oacc[nt], al, bh);
                mma_tf32(oacc[nt], ah, bl);
                mma_tf32(oacc[nt], ah, bh);
            }
        }
    }

    // ---- store O ----
    {
        int r1 = q0 + wm + g, r2 = r1 + 8;
#pragma unroll
        for (int nt = 0; nt < 2; nt++) {
            int col = wq + nt * 8 + 2 * t;
            if (r1 < STOK)
                *(float2*)(O + base + (size_t)r1 * DMODEL + col) = make_float2(oacc[nt][0], oacc[nt][1]);
            if (r2 < STOK)
                *(float2*)(O + base + (size_t)r2 * DMODEL + col) = make_float2(oacc[nt][2], oacc[nt][3]);
        }
    }
}

// ---------------------------------------------------------------------------
// Cosine-sim mask logits + mask LayerNorm -> (b, c, n)
// ---------------------------------------------------------------------------
__global__ __launch_bounds__(256) void classdot_ln_kernel(
    const float* __restrict__ pp, const float* __restrict__ cn,
    const float* __restrict__ mg, const float* __restrict__ mb,
    float* __restrict__ ms)
{
    __shared__ float p[768];
    __shared__ float dots[32];
    __shared__ float mv[2];
    __shared__ float scr[8];
    int n = blockIdx.x, b = blockIdx.y;
    int t = threadIdx.x;
    const float* prow = pp + ((size_t)b * NTOK + n) * DMODEL;
    float a0 = prow[t], a1 = prow[t + 256], a2 = prow[t + 512];
    p[t] = a0; p[t + 256] = a1; p[t + 512] = a2;
    float sq = block_reduce_sum(a0 * a0 + a1 * a1 + a2 * a2, scr);
    float pinv = rsqrtf(sq);
    __syncthreads();
    int w = t >> 5, lane = t & 31;
    for (int c = w; c < NCLS; c += 8) {
        const float* crow = cn + ((size_t)b * NCLS + c) * DMODEL;
        float s = 0.f;
        for (int d = lane; d < DMODEL; d += 32) s += p[d] * crow[d];
#pragma unroll
        for (int o = 16; o; o >>= 1) s += __shfl_xor_sync(0xffffffffu, s, o);
        if (!lane) dots[c] = s * pinv;
    }
    __syncthreads();
    if (t == 0) {
        float m = 0.f;
        for (int c = 0; c < NCLS; c++) m += dots[c];
        m *= (1.f / NCLS);
        float v = 0.f;
        for (int c = 0; c < NCLS; c++) { float d = dots[c] - m; v += d * d; }
        v *= (1.f / NCLS);
        mv[0] = m; mv[1] = rsqrtf(v + LN_EPS);
    }
    __syncthreads();
    if (t < NCLS)
        ms[((size_t)b * NCLS + t) * NTOK + n] = (dots[t] - mv[0]) * mv[1] * mg[t] + mb[t];
}

// ---------------------------------------------------------------------------
// Bilinear 32x32 -> 512x512
// ---------------------------------------------------------------------------
__global__ void resize_kernel(const float* __restrict__ ms, float* __restrict__ out)
{
    int i = blockIdx.x * blockDim.x + threadIdx.x;
    int xq = i & 127;
    int r  = i >> 7;
    int oy = r & 511; r >>= 9;
    int c  = r % NCLS;
    int b  = r / NCLS;
    const float* m = ms + ((size_t)b * NCLS + c) * NTOK;

    float fy = oy * 0.0625f - 0.46875f;
    float fyf = floorf(fy);
    float wy = fy - fyf;
    int y0 = (int)fyf, y1 = y0 + 1;
    y0 = max(0, min(31, y0));
    y1 = max(0, min(31, y1));
    const float* r0p = m + y0 * 32;
    const float* r1p = m + y1 * 32;

    float4 o4;
    float* po = (float*)&o4;
    int ox0 = xq * 4;
#pragma unroll
    for (int j = 0; j < 4; j++) {
        float fx = (ox0 + j) * 0.0625f - 0.46875f;
        float fxf = floorf(fx);
        float wx = fx - fxf;
        int x0 = (int)fxf, x1 = x0 + 1;
        x0 = max(0, min(31, x0));
        x1 = max(0, min(31, x1));
        float top = (1.f - wx) * r0p[x0] + wx * r0p[x1];
        float bot = (1.f - wx) * r1p[x0] + wx * r1p[x1];
        po[j] = (1.f - wy) * top + wy * bot;
    }
    *(float4*)(out + (((size_t)b * NCLS + c) * IMG + oy) * IMG + ox0) = o4;
}

// ---------------------------------------------------------------------------
// Host launcher
// ---------------------------------------------------------------------------
extern "C" void kernel_launch(void* const* d_in, const int* in_sizes, int n_in,
                              void* d_out, int out_size)
{
    const float* x          = (const float*)d_in[0];
    const float* proj_dec_W = (const float*)d_in[1];
    const float* proj_dec_b = (const float*)d_in[2];
    const float* cls_emb    = (const float*)d_in[3];
    const float* ln1_g      = (const float*)d_in[4];
    const float* ln1_b      = (const float*)d_in[5];
    const float* qW         = (const float*)d_in[6];
    const float* qb         = (const float*)d_in[7];
    const float* kW         = (const float*)d_in[8];
    const float* kb         = (const float*)d_in[9];
    const float* vW         = (const float*)d_in[10];
    const float* vb         = (const float*)d_in[11];
    const float* ln2_g      = (const float*)d_in[12];
    const float* ln2_b      = (const float*)d_in[13];
    const float* mlp_W1     = (const float*)d_in[14];
    const float* mlp_b1     = (const float*)d_in[15];
    const float* mlp_W2     = (const float*)d_in[16];
    const float* mlp_b2     = (const float*)d_in[17];
    const float* proj_patch = (const float*)d_in[18];
    const float* proj_cls   = (const float*)d_in[19];
    const float* dec_g      = (const float*)d_in[20];
    const float* dec_b      = (const float*)d_in[21];
    const float* mask_g     = (const float*)d_in[22];
    const float* mask_b     = (const float*)d_in[23];
    float* out = (float*)d_out;

    float *pTmp, *pX, *pH, *pQ, *pK, *pV, *pO, *pM1, *pPln, *pPP, *pCln, *pCP, *pCN, *pMS;
    cudaGetSymbolAddress((void**)&pTmp, g_Tmp);
    cudaGetSymbolAddress((void**)&pX,   g_X);
    cudaGetSymbolAddress((void**)&pH,   g_H);
    cudaGetSymbolAddress((void**)&pQ,   g_Q);
    cudaGetSymbolAddress((void**)&pK,   g_K);
    cudaGetSymbolAddress((void**)&pV,   g_V);
    cudaGetSymbolAddress((void**)&pO,   g_O);
    cudaGetSymbolAddress((void**)&pM1,  g_M1);
    cudaGetSymbolAddress((void**)&pPln, g_Pln);
    cudaGetSymbolAddress((void**)&pPP,  g_PP);
    cudaGetSymbolAddress((void**)&pCln, g_Cln);
    cudaGetSymbolAddress((void**)&pCP,  g_CP);
    cudaGetSymbolAddress((void**)&pCN,  g_CN);
    cudaGetSymbolAddress((void**)&pMS,  g_MS);

    cudaFuncSetAttribute(attn_mma_kernel, cudaFuncAttributeMaxDynamicSharedMemorySize, ATTN_SMEM);
    cudaFuncSetAttribute(gemm_tf32x3, cudaFuncAttributeMaxDynamicSharedMemorySize, GEMM_SMEM);

    // 1) proj_dec
    gemm_tf32x3<<<dim3(6, 64), 256, GEMM_SMEM>>>(x, DMODEL, proj_dec_W, DMODEL, proj_dec_b,
                                                 pTmp, DMODEL, BATCH * NTOK, DMODEL, DMODEL, 0);
    // 2) assemble
    assemble_kernel<<<(MTOT * DMODEL + 255) / 256, 256>>>(pTmp, cls_emb, pX);

    for (int l = 0; l < LAYERS; l++) {
        ln768_kernel<<<MTOT, 256>>>(pX, ln1_g + l * DMODEL, ln1_b + l * DMODEL, pH);
        qkv_kernel<<<dim3((MTOT + 63) / 64, HEADS, 3), 256>>>(
            pH, qW, qb, kW, kb, vW, vb, l, pQ, pK, pV);
        attn_mma_kernel<<<dim3((STOK + AQT - 1) / AQT, HEADS, BATCH), 256, ATTN_SMEM>>>(
            pQ, pK, pV, pO);
        // X += O, H = LN2(X)
        ln768_addres_kernel<<<MTOT, 256>>>(pX, pO, ln2_g + l * DMODEL, ln2_b + l * DMODEL, pH);
        gemm_tf32x3<<<dim3(24, (MTOT + 127) / 128), 256, GEMM_SMEM>>>(
            pH, DMODEL, mlp_W1 + (size_t)l * DMODEL * DMLP, DMLP, mlp_b1 + l * DMLP,
            pM1, DMLP, MTOT, DMLP, DMODEL, 1 /*gelu*/);
        gemm_tf32x3<<<dim3(6, (MTOT + 127) / 128), 256, GEMM_SMEM>>>(
            pM1, DMLP, mlp_W2 + (size_t)l * DMLP * DMODEL, DMODEL, mlp_b2 + l * DMODEL,
            pX, DMODEL, MTOT, DMODEL, DMLP, 2 /*accumulate*/);
    }

    lndec_kernel<<<MTOT, 256>>>(pX, dec_g, dec_b, pPln, pCln);
    gemm_tf32x3<<<dim3(6, 64), 256, GEMM_SMEM>>>(pPln, DMODEL, proj_patch, DMODEL, nullptr,
                                                 pPP, DMODEL, BATCH * NTOK, DMODEL, DMODEL, 0);
    gemm_tf32x3<<<dim3(6, 2), 256, GEMM_SMEM>>>(pCln, DMODEL, proj_cls, DMODEL, nullptr,
                                                pCP, DMODEL, BATCH * NCLS, DMODEL, DMODEL, 0);
    l2n_kernel<<<BATCH * NCLS, 256>>>(pCP, pCN);
    classdot_ln_kernel<<<dim3(NTOK, BATCH), 256>>>(pPP, pCN, mask_g, mask_b, pMS);
    resize_kernel<<<BATCH * NCLS * IMG * (IMG / 4) / 256, 256>>>(pMS, out);
}